// round 1
// baseline (speedup 1.0000x reference)
#include <cuda_runtime.h>
#include <math.h>

// QuantumTransformerBlock — fully fused, closed-form quantum ops + f32x2 FFN.
// B=32, S=2048, E=8, F=2048 -> N=65536 tokens.
// Inputs (metadata order): x, theta, phi, W1, b1, W2, b2, gamma1, beta1, gamma2, beta2

#define N_TOK 65536
#define SMEM_BYTES 147456  // 64KB W1 + 64KB W2^T + 16KB b1-packed

typedef unsigned long long u64;

__device__ __forceinline__ u64 fma2(u64 a, u64 b, u64 c) {
    u64 d; asm("fma.rn.f32x2 %0, %1, %2, %3;" : "=l"(d) : "l"(a), "l"(b), "l"(c)); return d;
}
__device__ __forceinline__ u64 mul2(u64 a, u64 b) {
    u64 d; asm("mul.rn.f32x2 %0, %1, %2;" : "=l"(d) : "l"(a), "l"(b)); return d;
}
__device__ __forceinline__ u64 add2(u64 a, u64 b) {
    u64 d; asm("add.rn.f32x2 %0, %1, %2;" : "=l"(d) : "l"(a), "l"(b)); return d;
}
__device__ __forceinline__ void unpack2(u64 a, float& lo, float& hi) {
    asm("mov.b64 {%0, %1}, %2;" : "=f"(lo), "=f"(hi) : "l"(a));
}
__device__ __forceinline__ u64 pack2(float lo, float hi) {
    u64 d; asm("mov.b64 %0, {%1, %2};" : "=l"(d) : "f"(lo), "f"(hi)); return d;
}

__global__ void __launch_bounds__(256, 1) qtb_kernel(
    const float* __restrict__ x, const float* __restrict__ theta, const float* __restrict__ phi,
    const float* __restrict__ W1, const float* __restrict__ b1,
    const float* __restrict__ W2, const float* __restrict__ b2,
    const float* __restrict__ g1, const float* __restrict__ be1,
    const float* __restrict__ g2, const float* __restrict__ be2,
    float* __restrict__ out)
{
    extern __shared__ float smem[];
    float*  sW1  = smem;                       // [2048][8], same layout as W1
    float*  sW2T = smem + 16384;               // [2048][8], transposed from W2[8][2048]
    float2* sB1  = (float2*)(smem + 32768);    // [2048] of (b1[f], 0)

    const int tid = threadIdx.x;
    for (int i = tid; i < 16384; i += 256) sW1[i] = W1[i];
    for (int i = tid; i < 16384; i += 256) {
        int e = i >> 11, f = i & 2047;
        sW2T[(f << 3) + e] = W2[i];            // coalesced read, strided smem write
    }
    for (int f = tid; f < 2048; f += 256) sB1[f] = make_float2(b1[f], 0.0f);
    __syncthreads();

    const int gt = blockIdx.x * 256 + tid;     // 0..32767
    if (gt >= (N_TOK >> 1)) return;
    const int t0 = gt << 1;                    // 2 adjacent tokens per thread

    // per-thread broadcast params (L1-hit, uniform)
    float th[8], cph[8], gg[8], bb[8];
    #pragma unroll
    for (int j = 0; j < 8; j++) {
        th[j]  = __ldg(theta + j);
        cph[j] = cosf(__ldg(phi + j));         // cos(phi_j), constant factor of z
        gg[j]  = __ldg(g1 + j);
        bb[j]  = __ldg(be1 + j);
    }

    float h0[8], h1[8];
    u64 zp0[4], zp1[4];

    #pragma unroll
    for (int tk = 0; tk < 2; tk++) {
        const float* xp = x + (size_t)(t0 + tk) * 8;
        float4 a4 = __ldg((const float4*)xp);
        float4 b4 = __ldg((const float4*)(xp + 4));
        float xv[8] = {a4.x, a4.y, a4.z, a4.w, b4.x, b4.y, b4.z, b4.w};

        // attn via Clifford identity: c_j = cos(x_j + theta_j)
        float c[8];
        #pragma unroll
        for (int j = 0; j < 8; j++) c[j] = cosf(xv[j] + th[j]);
        float attn[8];
        float p = c[0];
        #pragma unroll
        for (int j = 1; j < 8; j++) { p *= c[j]; attn[j] = p; }   // prod c_0..c_j
        float q = c[1];
        #pragma unroll
        for (int j = 2; j < 8; j++) q *= c[j];
        attn[0] = q;                                              // prod c_1..c_7

        // layernorm(x + attn)
        float y[8]; float s = 0.f;
        #pragma unroll
        for (int j = 0; j < 8; j++) { y[j] = xv[j] + attn[j]; s += y[j]; }
        float m = s * 0.125f, v = 0.f;
        #pragma unroll
        for (int j = 0; j < 8; j++) { float d = y[j] - m; v += d * d; }
        float inv = rsqrtf(v * 0.125f + 1e-5f);

        float* hh = tk ? h1 : h0;
        u64*   zz = tk ? zp1 : zp0;
        float z[8];
        #pragma unroll
        for (int j = 0; j < 8; j++) {
            hh[j] = (y[j] - m) * inv * gg[j] + bb[j];
            z[j]  = cph[j] * cosf(hh[j]);      // _ffn_quantum closed form
        }
        #pragma unroll
        for (int k = 0; k < 4; k++) zz[k] = pack2(z[2*k], z[2*k+1]);
    }

    // fused FFN: for each f: p = relu(dot(z, W1[f]) + b1[f]); acc_e += p * W2[e][f]
    u64 acc0[4] = {0,0,0,0}, acc1[4] = {0,0,0,0};
    const ulonglong2* w1p = (const ulonglong2*)sW1;
    const ulonglong2* w2p = (const ulonglong2*)sW2T;
    const u64*        bpp = (const u64*)sB1;

    #pragma unroll 4
    for (int f = 0; f < 2048; f++) {
        ulonglong2 A = w1p[2*f], B = w1p[2*f + 1];   // W1 row as 4 packed pairs
        u64 bp = bpp[f];                             // (b1[f], 0)

        u64 pA = fma2(zp0[0], A.x, bp);
        u64 pB = mul2(zp0[2], B.x);
        u64 qA = fma2(zp1[0], A.x, bp);
        u64 qB = mul2(zp1[2], B.x);
        pA = fma2(zp0[1], A.y, pA);
        pB = fma2(zp0[3], B.y, pB);
        qA = fma2(zp1[1], A.y, qA);
        qB = fma2(zp1[3], B.y, qB);

        float plo, phh, qlo, qhh;
        unpack2(add2(pA, pB), plo, phh);
        unpack2(add2(qA, qB), qlo, qhh);
        float r0 = fmaxf(plo + phh, 0.0f);
        float r1 = fmaxf(qlo + qhh, 0.0f);
        u64 rp0 = pack2(r0, r0);
        u64 rp1 = pack2(r1, r1);

        ulonglong2 C = w2p[2*f], D = w2p[2*f + 1];   // W2^T row: e-pairs
        acc0[0] = fma2(rp0, C.x, acc0[0]);
        acc0[1] = fma2(rp0, C.y, acc0[1]);
        acc0[2] = fma2(rp0, D.x, acc0[2]);
        acc0[3] = fma2(rp0, D.y, acc0[3]);
        acc1[0] = fma2(rp1, C.x, acc1[0]);
        acc1[1] = fma2(rp1, C.y, acc1[1]);
        acc1[2] = fma2(rp1, D.x, acc1[2]);
        acc1[3] = fma2(rp1, D.y, acc1[3]);
    }

    float g2v[8], b2e[8], bb2[8];
    #pragma unroll
    for (int j = 0; j < 8; j++) {
        g2v[j] = __ldg(g2 + j);
        b2e[j] = __ldg(be2 + j);
        bb2[j] = __ldg(b2 + j);
    }

    #pragma unroll
    for (int tk = 0; tk < 2; tk++) {
        u64*   aa = tk ? acc1 : acc0;
        float* hh = tk ? h1 : h0;
        float w[8];
        #pragma unroll
        for (int k = 0; k < 4; k++) { float lo, hi; unpack2(aa[k], lo, hi); w[2*k] = lo; w[2*k+1] = hi; }
        float s = 0.f;
        #pragma unroll
        for (int j = 0; j < 8; j++) { w[j] = hh[j] + w[j] + bb2[j]; s += w[j]; }
        float m = s * 0.125f, v = 0.f;
        #pragma unroll
        for (int j = 0; j < 8; j++) { float d = w[j] - m; v += d * d; }
        float inv = rsqrtf(v * 0.125f + 1e-5f);
        float o[8];
        #pragma unroll
        for (int j = 0; j < 8; j++) o[j] = (w[j] - m) * inv * g2v[j] + b2e[j];
        float* op = out + (size_t)(t0 + tk) * 8;
        *(float4*)op       = make_float4(o[0], o[1], o[2], o[3]);
        *(float4*)(op + 4) = make_float4(o[4], o[5], o[6], o[7]);
    }
}

extern "C" void kernel_launch(void* const* d_in, const int* in_sizes, int n_in,
                              void* d_out, int out_size) {
    const float* x      = (const float*)d_in[0];
    const float* theta  = (const float*)d_in[1];
    const float* phi    = (const float*)d_in[2];
    const float* W1     = (const float*)d_in[3];
    const float* b1     = (const float*)d_in[4];
    const float* W2     = (const float*)d_in[5];
    const float* b2     = (const float*)d_in[6];
    const float* gamma1 = (const float*)d_in[7];
    const float* beta1  = (const float*)d_in[8];
    const float* gamma2 = (const float*)d_in[9];
    const float* beta2  = (const float*)d_in[10];
    float* out = (float*)d_out;

    cudaFuncSetAttribute(qtb_kernel, cudaFuncAttributeMaxDynamicSharedMemorySize, SMEM_BYTES);
    qtb_kernel<<<128, 256, SMEM_BYTES>>>(x, theta, phi, W1, b1, W2, b2,
                                         gamma1, beta1, gamma2, beta2, out);
}